// round 5
// baseline (speedup 1.0000x reference)
#include <cuda_runtime.h>

// FeedForwardQuantum: out = relu(cos(x+theta) @ W1 + b1) @ W2 + b2
// ntok = B*S = 524288, E = 8, F = 32.
// R5 == R4 resubmitted (R4 run died to container infra, no signal):
// coalesced consecutive-token pairs + launch_bounds(128,6), UB-free lane
// assembly.

using ull = unsigned long long;

static constexpr int E = 8;
static constexpr int F = 32;

// ---- packed f32x2 helpers ------------------------------------------------
__device__ __forceinline__ ull pk2(float lo, float hi) {
    ull r; asm("mov.b64 %0, {%1,%2};" : "=l"(r) : "f"(lo), "f"(hi)); return r;
}
__device__ __forceinline__ void up2(ull v, float& lo, float& hi) {
    asm("mov.b64 {%0,%1}, %2;" : "=f"(lo), "=f"(hi) : "l"(v));
}
__device__ __forceinline__ ull dup2(float f) {
    ull r; asm("mov.b64 %0, {%1,%1};" : "=l"(r) : "f"(f)); return r;
}
__device__ __forceinline__ ull fma2(ull a, ull b, ull c) {
    ull r; asm("fma.rn.f32x2 %0, %1, %2, %3;" : "=l"(r) : "l"(a), "l"(b), "l"(c)); return r;
}
__device__ __forceinline__ ull add2(ull a, ull b) {
    ull r; asm("add.rn.f32x2 %0, %1, %2;" : "=l"(r) : "l"(a), "l"(b)); return r;
}
__device__ __forceinline__ ull mul2(ull a, ull b) {
    ull r; asm("mul.rn.f32x2 %0, %1, %2;" : "=l"(r) : "l"(a), "l"(b)); return r;
}

// ---- packed cosine: 2pi Cody-Waite reduction + even Taylor deg-14 --------
// Max abs error ~1e-6 on the reduced range — far under the 1e-3 budget.
__device__ __forceinline__ ull pcos2(ull a) {
    const ull inv2pi = dup2(0.15915494309189535f);
    const ull mag    = dup2(12582912.0f);           // 1.5*2^23 round magic
    const ull nmag   = dup2(-12582912.0f);
    const ull nhi    = dup2(-6.28318548202514648f); // -float(2*pi)
    const ull plo    = dup2(1.74845553e-7f);
    ull km = fma2(a, inv2pi, mag);
    ull k  = add2(km, nmag);
    ull r  = fma2(k, nhi, a);
    r      = fma2(k, plo, r);            // r in [-pi, pi]
    ull t  = mul2(r, r);
    ull p  = fma2(dup2(-1.14707456e-11f), t, dup2(2.08767570e-9f));
    p = fma2(p, t, dup2(-2.75573192e-7f));
    p = fma2(p, t, dup2(2.48015873e-5f));
    p = fma2(p, t, dup2(-1.38888889e-3f));
    p = fma2(p, t, dup2(4.16666667e-2f));
    p = fma2(p, t, dup2(-0.5f));
    p = fma2(p, t, dup2(1.0f));
    return p;
}

// ---- kernel --------------------------------------------------------------
// 128 threads/block, 4 tokens/thread as 2 packed pairs of CONSECUTIVE tokens:
//   pair0 = tokens (wbase + 2*lane, +1)       covering [wbase, wbase+64)
//   pair1 = tokens (wbase + 64 + 2*lane, +1)  covering [wbase+64, wbase+128)
// Lane address stride is 64B -> minimal L1tex line-wavefronts per LDG/STG.
__global__ __launch_bounds__(128, 6)
void ffq_kernel(const float* __restrict__ x,
                const float* __restrict__ theta,
                const float* __restrict__ w1,
                const float* __restrict__ b1,
                const float* __restrict__ w2,
                const float* __restrict__ b2,
                float* __restrict__ out,
                int ntok) {
    // Weights duplicated into both f32x2 halves; w1 stored transposed [F][E].
    __shared__ __align__(16) ull s_w1d[F * E];
    __shared__ __align__(16) ull s_w2d[F * E];
    __shared__ __align__(16) ull s_b1d[F];
    __shared__ __align__(16) ull s_b2d[E];
    __shared__ __align__(16) ull s_thd[E];

    const int tid = threadIdx.x;
    for (int i = tid; i < F * E; i += 128) {
        int e = i & 7, f = i >> 3;
        s_w1d[i] = dup2(w1[e * F + f]);   // transpose to [F][E]
        s_w2d[i] = dup2(w2[i]);           // already [F][E]
    }
    if (tid < F) s_b1d[tid] = dup2(b1[tid]);
    if (tid < E) { s_b2d[tid] = dup2(b2[tid]); s_thd[tid] = dup2(theta[tid]); }
    __syncthreads();

    const int lane = tid & 31;
    const int warp = tid >> 5;
    const int wbase = blockIdx.x * 512 + warp * 128;
    const int tA = wbase + 2 * lane;        // pair0 tokens: tA, tA+1
    const int tB = wbase + 64 + 2 * lane;   // pair1 tokens: tB, tB+1

    const float4* x4 = reinterpret_cast<const float4*>(x);

    // Issue all 8 LDG.128 up front (MLP=8), clamped for tail safety.
    int iA = 2 * min(tA, ntok - 2);
    int iB = 2 * min(tB, ntok - 2);
    float4 a0 = x4[iA + 0], a1 = x4[iA + 1], a2 = x4[iA + 2], a3 = x4[iA + 3];
    float4 b0 = x4[iB + 0], b1q = x4[iB + 1], b2q = x4[iB + 2], b3q = x4[iB + 3];

    // Explicit lane assembly (NO cross-object pointer arithmetic).
    float xA0[8] = {a0.x, a0.y, a0.z, a0.w, a1.x, a1.y, a1.z, a1.w};   // token tA
    float xA1[8] = {a2.x, a2.y, a2.z, a2.w, a3.x, a3.y, a3.z, a3.w};   // token tA+1
    float xB0[8] = {b0.x, b0.y, b0.z, b0.w, b1q.x, b1q.y, b1q.z, b1q.w}; // token tB
    float xB1[8] = {b2q.x, b2q.y, b2q.z, b2q.w, b3q.x, b3q.y, b3q.z, b3q.w}; // tB+1

    ull q2[2][E];
#pragma unroll
    for (int e = 0; e < E; ++e)
        q2[0][e] = pcos2(add2(pk2(xA0[e], xA1[e]), s_thd[e]));
#pragma unroll
    for (int e = 0; e < E; ++e)
        q2[1][e] = pcos2(add2(pk2(xB0[e], xB1[e]), s_thd[e]));

    ull o2[2][E];
#pragma unroll
    for (int p = 0; p < 2; ++p)
#pragma unroll
        for (int e = 0; e < E; ++e) o2[p][e] = s_b2d[e];

#pragma unroll 8
    for (int f = 0; f < F; ++f) {
        const ulonglong2* w1r = reinterpret_cast<const ulonglong2*>(&s_w1d[f * E]);
        const ulonglong2* w2r = reinterpret_cast<const ulonglong2*>(&s_w2d[f * E]);
        ulonglong2 w1v0 = w1r[0], w1v1 = w1r[1], w1v2 = w1r[2], w1v3 = w1r[3];
        ulonglong2 w2v0 = w2r[0], w2v1 = w2r[1], w2v2 = w2r[2], w2v3 = w2r[3];
        ull b1d = s_b1d[f];
#pragma unroll
        for (int p = 0; p < 2; ++p) {
            ull h = b1d;
            h = fma2(q2[p][0], w1v0.x, h);
            h = fma2(q2[p][1], w1v0.y, h);
            h = fma2(q2[p][2], w1v1.x, h);
            h = fma2(q2[p][3], w1v1.y, h);
            h = fma2(q2[p][4], w1v2.x, h);
            h = fma2(q2[p][5], w1v2.y, h);
            h = fma2(q2[p][6], w1v3.x, h);
            h = fma2(q2[p][7], w1v3.y, h);
            // ReLU per half on the ALU pipe (FMNMX) — no fma-pipe contention.
            float hl, hh;
            up2(h, hl, hh);
            hl = fmaxf(hl, 0.0f);
            hh = fmaxf(hh, 0.0f);
            h = pk2(hl, hh);
            o2[p][0] = fma2(h, w2v0.x, o2[p][0]);
            o2[p][1] = fma2(h, w2v0.y, o2[p][1]);
            o2[p][2] = fma2(h, w2v1.x, o2[p][2]);
            o2[p][3] = fma2(h, w2v1.y, o2[p][3]);
            o2[p][4] = fma2(h, w2v2.x, o2[p][4]);
            o2[p][5] = fma2(h, w2v2.y, o2[p][5]);
            o2[p][6] = fma2(h, w2v3.x, o2[p][6]);
            o2[p][7] = fma2(h, w2v3.y, o2[p][7]);
        }
    }

    float4* o4 = reinterpret_cast<float4*>(out);
#pragma unroll
    for (int p = 0; p < 2; ++p) {
        float lo[8], hi[8];
#pragma unroll
        for (int e = 0; e < E; ++e) up2(o2[p][e], lo[e], hi[e]);
        int t0 = p ? tB : tA;          // tokens t0, t0+1
        if (t0 + 1 < ntok) {
            o4[t0 * 2 + 0] = make_float4(lo[0], lo[1], lo[2], lo[3]);
            o4[t0 * 2 + 1] = make_float4(lo[4], lo[5], lo[6], lo[7]);
            o4[t0 * 2 + 2] = make_float4(hi[0], hi[1], hi[2], hi[3]);
            o4[t0 * 2 + 3] = make_float4(hi[4], hi[5], hi[6], hi[7]);
        } else if (t0 < ntok) {
            o4[t0 * 2 + 0] = make_float4(lo[0], lo[1], lo[2], lo[3]);
            o4[t0 * 2 + 1] = make_float4(lo[4], lo[5], lo[6], lo[7]);
        }
    }
}

extern "C" void kernel_launch(void* const* d_in, const int* in_sizes, int n_in,
                              void* d_out, int out_size) {
    const float* x     = (const float*)d_in[0];
    const float* theta = (const float*)d_in[1];
    const float* w1    = (const float*)d_in[2];
    const float* b1    = (const float*)d_in[3];
    const float* w2    = (const float*)d_in[4];
    const float* b2    = (const float*)d_in[5];
    float* out = (float*)d_out;

    int ntok = out_size / E;                    // B*S (output is [ntok, E])
    if (ntok <= 0) ntok = in_sizes[0] / E;
    int grid = (ntok + 511) / 512;              // 512 tokens per block
    ffq_kernel<<<grid, 128>>>(x, theta, w1, b1, w2, b2, out, ntok);
}

// round 6
// speedup vs baseline: 1.3384x; 1.3384x over previous
#include <cuda_runtime.h>

// FeedForwardQuantum: out = relu(cos(x+theta) @ W1 + b1) @ W2 + b2
// ntok = B*S = 524288, E = 8, F = 32.
// R6: repack f32x2 over (e,e+1)/(f,f+1) instead of over tokens.
//  -> weights need NO duplication (halved LDS bytes), one 128B record per
//     f-pair serves both tokens (LDS instr /thread: 290 -> ~150),
//  -> cos work halves (4 packed pcos2 per token),
//  -> biases folded via (bias, 0) seeds + one horizontal add.
// regs ~100 @ launch_bounds(128,4): no spills (R5 lesson).

using ull = unsigned long long;

static constexpr int E = 8;
static constexpr int F = 32;

// ---- packed f32x2 helpers ------------------------------------------------
__device__ __forceinline__ ull pk2(float lo, float hi) {
    ull r; asm("mov.b64 %0, {%1,%2};" : "=l"(r) : "f"(lo), "f"(hi)); return r;
}
__device__ __forceinline__ void up2(ull v, float& lo, float& hi) {
    asm("mov.b64 {%0,%1}, %2;" : "=f"(lo), "=f"(hi) : "l"(v));
}
__device__ __forceinline__ ull dup2(float f) {
    ull r; asm("mov.b64 %0, {%1,%1};" : "=l"(r) : "f"(f)); return r;
}
__device__ __forceinline__ ull fma2(ull a, ull b, ull c) {
    ull r; asm("fma.rn.f32x2 %0, %1, %2, %3;" : "=l"(r) : "l"(a), "l"(b), "l"(c)); return r;
}
__device__ __forceinline__ ull add2(ull a, ull b) {
    ull r; asm("add.rn.f32x2 %0, %1, %2;" : "=l"(r) : "l"(a), "l"(b)); return r;
}
__device__ __forceinline__ ull mul2(ull a, ull b) {
    ull r; asm("mul.rn.f32x2 %0, %1, %2;" : "=l"(r) : "l"(a), "l"(b)); return r;
}

// ---- packed cosine: 2pi Cody-Waite + even Taylor deg-14 (err ~1e-6) ------
__device__ __forceinline__ ull pcos2(ull a) {
    ull km = fma2(a, dup2(0.15915494309189535f), dup2(12582912.0f));
    ull k  = add2(km, dup2(-12582912.0f));
    ull r  = fma2(k, dup2(-6.28318548202514648f), a);
    r      = fma2(k, dup2(1.74845553e-7f), r);      // r in [-pi, pi]
    ull t  = mul2(r, r);
    ull p  = fma2(dup2(-1.14707456e-11f), t, dup2(2.08767570e-9f));
    p = fma2(p, t, dup2(-2.75573192e-7f));
    p = fma2(p, t, dup2(2.48015873e-5f));
    p = fma2(p, t, dup2(-1.38888889e-3f));
    p = fma2(p, t, dup2(4.16666667e-2f));
    p = fma2(p, t, dup2(-0.5f));
    p = fma2(p, t, dup2(1.0f));
    return p;
}

// ---- kernel --------------------------------------------------------------
// 128 thr/block, 2 tokens/thread: lane l of warp w handles tokens
// wbase + l and wbase + l + 32  (lane stride 32B -> 4 lanes per 128B line,
// minimal L1tex wavefronts for LDG/STG).
//
// Shared record per f-pair fp (f = 2fp, 2fp+1), 16 ull = 128B:
//   [0..3] : (w1[2ep][fA], w1[2ep+1][fA])  ep=0..3     (GEMM1 row fA)
//   [4..7] : same for fB
//   [8..15]: (w2[fA][e],  w2[fB][e])       e=0..7      (GEMM2 slice)
__global__ __launch_bounds__(128, 4)
void ffq_kernel(const float* __restrict__ x,
                const float* __restrict__ theta,
                const float* __restrict__ w1,
                const float* __restrict__ b1,
                const float* __restrict__ w2,
                const float* __restrict__ b2,
                float* __restrict__ out,
                int ntok) {
    __shared__ __align__(16) ull s_blk[16 * 16];
    __shared__ __align__(16) ull s_seed[F];     // (b1[f], 0)
    __shared__ __align__(16) ull s_b2p[E];      // (b2[e], 0)
    __shared__ __align__(16) ull s_th[4];       // (theta[2i], theta[2i+1])

    const int tid = threadIdx.x;
    for (int i = tid; i < 256; i += 128) {
        int fp = i >> 4, j = i & 15;
        int fA = 2 * fp, fB = fA + 1;
        ull v;
        if (j < 4) {
            int ep = j;
            v = pk2(w1[(2 * ep) * F + fA], w1[(2 * ep + 1) * F + fA]);
        } else if (j < 8) {
            int ep = j - 4;
            v = pk2(w1[(2 * ep) * F + fB], w1[(2 * ep + 1) * F + fB]);
        } else {
            int e = j - 8;
            v = pk2(w2[fA * E + e], w2[fB * E + e]);
        }
        s_blk[i] = v;
    }
    if (tid < F) s_seed[tid] = pk2(b1[tid], 0.0f);
    if (tid < E) s_b2p[tid] = pk2(b2[tid], 0.0f);
    if (tid < 4) s_th[tid] = pk2(theta[2 * tid], theta[2 * tid + 1]);
    __syncthreads();

    const int lane = tid & 31;
    const int warp = tid >> 5;
    const int wbase = blockIdx.x * 256 + warp * 64;
    const int t0 = wbase + lane;
    const int t1 = t0 + 32;

    const float4* x4 = reinterpret_cast<const float4*>(x);
    int i0 = 2 * min(t0, ntok - 1);
    int i1 = 2 * min(t1, ntok - 1);
    float4 a0 = x4[i0], a1 = x4[i0 + 1];
    float4 c0 = x4[i1], c1 = x4[i1 + 1];

    ull th0 = s_th[0], th1 = s_th[1], th2 = s_th[2], th3 = s_th[3];

    // q[token][ep] = cos(x[2ep..2ep+1] + theta[2ep..2ep+1]) packed over e.
    ull q[2][4];
    q[0][0] = pcos2(add2(pk2(a0.x, a0.y), th0));
    q[0][1] = pcos2(add2(pk2(a0.z, a0.w), th1));
    q[0][2] = pcos2(add2(pk2(a1.x, a1.y), th2));
    q[0][3] = pcos2(add2(pk2(a1.z, a1.w), th3));
    q[1][0] = pcos2(add2(pk2(c0.x, c0.y), th0));
    q[1][1] = pcos2(add2(pk2(c0.z, c0.w), th1));
    q[1][2] = pcos2(add2(pk2(c1.x, c1.y), th2));
    q[1][3] = pcos2(add2(pk2(c1.z, c1.w), th3));

    // o[token][e]: f-packed partial sums, seeded (b2[e], 0).
    ull o[2][E];
#pragma unroll
    for (int tk = 0; tk < 2; ++tk)
#pragma unroll
        for (int e = 0; e < E; ++e) o[tk][e] = s_b2p[e];

#pragma unroll
    for (int fp = 0; fp < 16; ++fp) {
        const ulonglong2* rec = reinterpret_cast<const ulonglong2*>(&s_blk[fp * 16]);
        ulonglong2 wa0 = rec[0], wa1 = rec[1];   // GEMM1 row fA (4 e-pairs)
        ulonglong2 wb0 = rec[2], wb1 = rec[3];   // GEMM1 row fB
        ulonglong2 w20 = rec[4], w21 = rec[5], w22 = rec[6], w23 = rec[7];
        ull sA = s_seed[2 * fp], sB = s_seed[2 * fp + 1];
#pragma unroll
        for (int tk = 0; tk < 2; ++tk) {
            // GEMM1: two 4-deep chains, seeded with (b1, 0).
            ull cA = fma2(q[tk][0], wa0.x, sA);
            cA = fma2(q[tk][1], wa0.y, cA);
            cA = fma2(q[tk][2], wa1.x, cA);
            cA = fma2(q[tk][3], wa1.y, cA);
            ull cB = fma2(q[tk][0], wb0.x, sB);
            cB = fma2(q[tk][1], wb0.y, cB);
            cB = fma2(q[tk][2], wb1.x, cB);
            cB = fma2(q[tk][3], wb1.y, cB);
            // horizontal add (register-pair split is free) + ReLU.
            float lA, hAv, lB, hBv;
            up2(cA, lA, hAv);
            up2(cB, lB, hBv);
            float hA = fmaxf(lA + hAv, 0.0f);
            float hB = fmaxf(lB + hBv, 0.0f);
            ull h2 = pk2(hA, hB);
            // GEMM2: 8 independent f-packed accumulations.
            o[tk][0] = fma2(h2, w20.x, o[tk][0]);
            o[tk][1] = fma2(h2, w20.y, o[tk][1]);
            o[tk][2] = fma2(h2, w21.x, o[tk][2]);
            o[tk][3] = fma2(h2, w21.y, o[tk][3]);
            o[tk][4] = fma2(h2, w22.x, o[tk][4]);
            o[tk][5] = fma2(h2, w22.y, o[tk][5]);
            o[tk][6] = fma2(h2, w23.x, o[tk][6]);
            o[tk][7] = fma2(h2, w23.y, o[tk][7]);
        }
    }

    float4* o4 = reinterpret_cast<float4*>(out);
#pragma unroll
    for (int tk = 0; tk < 2; ++tk) {
        float r[E];
#pragma unroll
        for (int e = 0; e < E; ++e) {
            float lo, hi;
            up2(o[tk][e], lo, hi);
            r[e] = lo + hi;                     // absorbs b2 seed
        }
        int t = tk ? t1 : t0;
        if (t < ntok) {
            o4[t * 2 + 0] = make_float4(r[0], r[1], r[2], r[3]);
            o4[t * 2 + 1] = make_float4(r[4], r[5], r[6], r[7]);
        }
    }
}

extern "C" void kernel_launch(void* const* d_in, const int* in_sizes, int n_in,
                              void* d_out, int out_size) {
    const float* x     = (const float*)d_in[0];
    const float* theta = (const float*)d_in[1];
    const float* w1    = (const float*)d_in[2];
    const float* b1    = (const float*)d_in[3];
    const float* w2    = (const float*)d_in[4];
    const float* b2    = (const float*)d_in[5];
    float* out = (float*)d_out;

    int ntok = out_size / E;                    // B*S (output is [ntok, E])
    if (ntok <= 0) ntok = in_sizes[0] / E;
    int grid = (ntok + 255) / 256;              // 256 tokens per block
    ffq_kernel<<<grid, 128>>>(x, theta, w1, b1, w2, b2, out, ntok);
}